// round 1
// baseline (speedup 1.0000x reference)
#include <cuda_runtime.h>
#include <cuda_bf16.h>
#include <cstdint>

// Problem constants (fixed by setup_inputs)
#define HPM      8
#define NUM_PAGES 4096
#define PAGE_SIZE 16
#define DPM      128
#define MAX_SEQS 8
#define MAX_PPS  256
#define D4       (DPM / 4)                       // 32 float4 per row
#define PAGES_ELEMS (2LL * HPM * NUM_PAGES * PAGE_SIZE * DPM)  // 134,217,728
#define INNER_F4 (HPM * NUM_PAGES * PAGE_SIZE * D4)            // per-tensor float4 count = 1<<24
#define TOTAL_F4 (2 * INNER_F4)                                // 1<<25

// Scratch (device globals — no allocation allowed)
__device__ int g_blk_of_page[NUM_PAGES];   // -1 if page keeps its old contents, else block index
__device__ int g_page_of_block[MAX_PPS];
__device__ int g_num_blocks;

// ---------------------------------------------------------------------------
// Kernel A: first-fit allocation scan over page_indices, fills the mapping
// tables, and writes the two small outputs (as float32).
// One block, 1024 threads, 4 pages/thread.
// ---------------------------------------------------------------------------
__global__ void __launch_bounds__(1024)
setup_kernel(const int* __restrict__ page_indices,
             const int* __restrict__ seq_page_indices,
             const int* __restrict__ slot_p,
             const int* __restrict__ true_length_p,
             float* __restrict__ out_pi,
             float* __restrict__ out_spi)
{
    __shared__ int s_cnt[1024];
    const int tid = threadIdx.x;

    // Local free flags (page 0 is reserved)
    int local[4];
    int cnt = 0;
#pragma unroll
    for (int j = 0; j < 4; j++) {
        int p  = tid * 4 + j;
        int fr = (p >= 1) && (page_indices[p] == 0);
        local[j] = fr;
        cnt += fr;
    }
    s_cnt[tid] = cnt;
    __syncthreads();

    // Hillis-Steele inclusive scan over 1024 partial counts
    for (int off = 1; off < 1024; off <<= 1) {
        int add = (tid >= off) ? s_cnt[tid - off] : 0;
        __syncthreads();
        s_cnt[tid] += add;
        __syncthreads();
    }
    const int excl = (tid == 0) ? 0 : s_cnt[tid - 1];

    const int tl = true_length_p[0];
    int nb = (tl + PAGE_SIZE - 1) / PAGE_SIZE;
    if (nb > MAX_PPS) nb = MAX_PPS;

    // Assign block indices to the first nb free pages; emit page_indices output
    int run = excl;
#pragma unroll
    for (int j = 0; j < 4; j++) {
        int p = tid * 4 + j;
        int b = -1;
        if (local[j]) {
            if (run < nb) { b = run; g_page_of_block[run] = p; }
            run++;
        }
        g_blk_of_page[p] = b;
        out_pi[p] = (b >= 0) ? 1.0f : (float)page_indices[p];
    }
    if (tid == 0) g_num_blocks = nb;
    __syncthreads();  // orders g_page_of_block writes before reads below (block scope)

    // seq_page_indices output (8 x 256), row `slot` gets the allocated page ids
    const int slot = slot_p[0];
    for (int i = tid; i < MAX_SEQS * MAX_PPS; i += 1024) {
        int r = i >> 8, c = i & 255;
        float v = (float)seq_page_indices[i];
        if (r == slot && c < nb) v = (float)g_page_of_block[c];
        out_spi[i] = v;
    }
}

// ---------------------------------------------------------------------------
// Kernel B: single-pass assembly of the [2, H, P, PS, D] pages output.
// One float4 per thread; source is either key/value (allocated pages, with
// the [S,H,D] -> [H,S,D] transpose folded into the index) or the original
// key_pages/value_pages. Warp-uniform blk_of_page lookup (one load/warp).
// ---------------------------------------------------------------------------
__global__ void __launch_bounds__(256)
assemble_pages_kernel(const float4* __restrict__ key,      // [1, S, H, D]
                      const float4* __restrict__ value,
                      const float4* __restrict__ key_pages,   // [H, P, PS, D]
                      const float4* __restrict__ value_pages,
                      float4* __restrict__ out)               // [2, H, P, PS, D]
{
    unsigned idx = blockIdx.x * 256u + threadIdx.x;   // < TOTAL_F4 = 1<<25

    // Decode (all power-of-two dims): [t, h, p, row, d4]
    unsigned v   = idx;
    unsigned d4  = v & (D4 - 1);        v >>= 5;
    unsigned row = v & (PAGE_SIZE - 1); v >>= 4;
    unsigned p   = v & (NUM_PAGES - 1); v >>= 12;
    unsigned h   = v & (HPM - 1);       v >>= 3;
    unsigned t   = v;                    // 0 = key, 1 = value

    int b = __ldg(&g_blk_of_page[p]);    // warp-uniform (warp spans d4 only)

    float4 val;
    if (b >= 0) {
        // source = key/value[0, b*16+row, h, d]  (transpose folded in)
        unsigned s   = (unsigned)b * PAGE_SIZE + row;
        unsigned off = (s * HPM + h) * D4 + d4;
        val = t ? __ldg(&value[off]) : __ldg(&key[off]);
    } else {
        // source = original pages tensor at the identical intra-tensor offset
        unsigned off = idx & (INNER_F4 - 1);
        val = t ? __ldg(&value_pages[off]) : __ldg(&key_pages[off]);
    }
    out[idx] = val;
}

// ---------------------------------------------------------------------------
// Launch
// Inputs (metadata order): key, value, key_pages, value_pages,
//                          page_indices, seq_page_indices, slot, true_length
// Output: concat(pages[2,H,P,PS,D], page_indices[4096], seq_page_indices[2048])
// ---------------------------------------------------------------------------
extern "C" void kernel_launch(void* const* d_in, const int* in_sizes, int n_in,
                              void* d_out, int out_size)
{
    const float* key          = (const float*)d_in[0];
    const float* value        = (const float*)d_in[1];
    const float* key_pages    = (const float*)d_in[2];
    const float* value_pages  = (const float*)d_in[3];
    const int*   page_indices = (const int*)d_in[4];
    const int*   seq_page_ind = (const int*)d_in[5];
    const int*   slot         = (const int*)d_in[6];
    const int*   true_length  = (const int*)d_in[7];

    float* out_pages = (float*)d_out;
    float* out_pi    = out_pages + PAGES_ELEMS;
    float* out_spi   = out_pi + NUM_PAGES;

    setup_kernel<<<1, 1024>>>(page_indices, seq_page_ind, slot, true_length,
                              out_pi, out_spi);

    const unsigned nblocks = TOTAL_F4 / 256;   // 131072
    assemble_pages_kernel<<<nblocks, 256>>>(
        (const float4*)key, (const float4*)value,
        (const float4*)key_pages, (const float4*)value_pages,
        (float4*)out_pages);
}

// round 2
// speedup vs baseline: 1.0578x; 1.0578x over previous
#include <cuda_runtime.h>
#include <cuda_bf16.h>
#include <cstdint>

// Problem constants (fixed by setup_inputs)
#define HPM       8
#define NUM_PAGES 4096
#define PAGE_SIZE 16
#define DPM       128
#define MAX_SEQS  8
#define MAX_PPS   256
#define D4        (DPM / 4)                                    // 32 float4 per row
#define PAGES_ELEMS (2LL * HPM * NUM_PAGES * PAGE_SIZE * DPM)  // 134,217,728 floats
#define INNER_F4  (HPM * NUM_PAGES * PAGE_SIZE * D4)           // 1<<24 float4 per tensor
#define TOTAL_F4  (2u * INNER_F4)                              // 1<<25

// Scratch (device globals — no allocation allowed)
__device__ int g_blk_of_page[NUM_PAGES];   // -1 => keep old page contents, else block index
__device__ int g_page_of_block[MAX_PPS];

// ---------------------------------------------------------------------------
// Kernel A: first-fit allocation + small outputs. 1024 threads, 4 pages each.
// Warp-shuffle scan (2 barriers total instead of 20).
// ---------------------------------------------------------------------------
__global__ void __launch_bounds__(1024)
setup_kernel(const int* __restrict__ page_indices,
             const int* __restrict__ seq_page_indices,
             const int* __restrict__ slot_p,
             const int* __restrict__ true_length_p,
             float* __restrict__ out_pi,
             float* __restrict__ out_spi)
{
    __shared__ int s_wsum[32];
    const int tid  = threadIdx.x;
    const int lane = tid & 31;
    const int wid  = tid >> 5;

    // Free flags (page 0 reserved)
    int local[4];
    int cnt = 0;
#pragma unroll
    for (int j = 0; j < 4; j++) {
        int p  = tid * 4 + j;
        int fr = (p >= 1) && (page_indices[p] == 0);
        local[j] = fr;
        cnt += fr;
    }

    // Warp inclusive scan of per-thread counts
    int incl = cnt;
#pragma unroll
    for (int off = 1; off < 32; off <<= 1) {
        int n = __shfl_up_sync(0xffffffffu, incl, off);
        if (lane >= off) incl += n;
    }
    if (lane == 31) s_wsum[wid] = incl;
    __syncthreads();

    // Warp 0 scans the 32 warp totals (exclusive)
    if (wid == 0) {
        int v = s_wsum[lane];
        int s = v;
#pragma unroll
        for (int off = 1; off < 32; off <<= 1) {
            int n = __shfl_up_sync(0xffffffffu, s, off);
            if (lane >= off) s += n;
        }
        s_wsum[lane] = s - v;   // exclusive warp base
    }
    __syncthreads();

    const int excl = s_wsum[wid] + (incl - cnt);

    const int tl = true_length_p[0];
    int nb = (tl + PAGE_SIZE - 1) / PAGE_SIZE;
    if (nb > MAX_PPS) nb = MAX_PPS;

    // Assign block indices to the first nb free pages; emit page_indices output
    int run = excl;
#pragma unroll
    for (int j = 0; j < 4; j++) {
        int p = tid * 4 + j;
        int b = -1;
        if (local[j]) {
            if (run < nb) { b = run; g_page_of_block[run] = p; }
            run++;
        }
        g_blk_of_page[p] = b;
        out_pi[p] = (b >= 0) ? 1.0f : (float)page_indices[p];
    }
    __syncthreads();  // g_page_of_block writes visible block-wide

    // seq_page_indices output (8 x 256)
    const int slot = slot_p[0];
    for (int i = tid; i < MAX_SEQS * MAX_PPS; i += 1024) {
        int r = i >> 8, c = i & 255;
        float v = (float)seq_page_indices[i];
        if (r == slot && c < nb) v = (float)g_page_of_block[c];
        out_spi[i] = v;
    }
}

// ---------------------------------------------------------------------------
// Kernel B: assemble [2, H, P, PS, D]. 4 float4 per thread; the 4 loads are
// independent and issued back-to-back (MLP_p1=4). Tensor select (k vs v) is
// block-uniform (1<<24 boundary aligns with the 1024-f4 block span), so it is
// hoisted. Per-element source select is a predicated pointer select.
// ---------------------------------------------------------------------------
__global__ void __launch_bounds__(256)
assemble_pages_kernel(const float4* __restrict__ key,        // [1, S, H, D]
                      const float4* __restrict__ value,
                      const float4* __restrict__ key_pages,  // [H, P, PS, D]
                      const float4* __restrict__ value_pages,
                      float4* __restrict__ out)               // [2, H, P, PS, D]
{
    const unsigned base = blockIdx.x * 1024u + threadIdx.x;  // block covers 1024 f4
    const unsigned t = base >> 24;                            // 0 = key, 1 = value (uniform)
    const float4* __restrict__ kv    = t ? value       : key;
    const float4* __restrict__ pages = t ? value_pages : key_pages;

    const float4* srcs[4];
#pragma unroll
    for (int j = 0; j < 4; j++) {
        unsigned idx = base + j * 256u;
        unsigned v   = idx;
        unsigned d4  = v & (D4 - 1);        v >>= 5;
        unsigned row = v & (PAGE_SIZE - 1); v >>= 4;
        unsigned p   = v & (NUM_PAGES - 1); v >>= 12;
        unsigned h   = v & (HPM - 1);

        int b = g_blk_of_page[p];           // warp-uniform lookup (L2-resident 16KB)
        unsigned s    = (unsigned)b * PAGE_SIZE + row;
        unsigned offA = (s * HPM + h) * D4 + d4;       // key/value (transpose folded)
        unsigned offB = idx & (INNER_F4 - 1);          // pass-through pages
        srcs[j] = (b >= 0) ? (kv + offA) : (pages + offB);
    }

    float4 vals[4];
#pragma unroll
    for (int j = 0; j < 4; j++) vals[j] = __ldg(srcs[j]);   // 4 back-to-back LDG.128

#pragma unroll
    for (int j = 0; j < 4; j++) out[base + j * 256u] = vals[j];
}

// ---------------------------------------------------------------------------
// Launch
// Inputs: key, value, key_pages, value_pages, page_indices, seq_page_indices,
//         slot, true_length
// Output: concat(pages[2,H,P,PS,D], page_indices[4096], seq_page_indices[2048])
// ---------------------------------------------------------------------------
extern "C" void kernel_launch(void* const* d_in, const int* in_sizes, int n_in,
                              void* d_out, int out_size)
{
    const float* key          = (const float*)d_in[0];
    const float* value        = (const float*)d_in[1];
    const float* key_pages    = (const float*)d_in[2];
    const float* value_pages  = (const float*)d_in[3];
    const int*   page_indices = (const int*)d_in[4];
    const int*   seq_page_ind = (const int*)d_in[5];
    const int*   slot         = (const int*)d_in[6];
    const int*   true_length  = (const int*)d_in[7];

    float* out_pages = (float*)d_out;
    float* out_pi    = out_pages + PAGES_ELEMS;
    float* out_spi   = out_pi + NUM_PAGES;

    setup_kernel<<<1, 1024>>>(page_indices, seq_page_ind, slot, true_length,
                              out_pi, out_spi);

    const unsigned nblocks = TOTAL_F4 / 1024;   // 32768
    assemble_pages_kernel<<<nblocks, 256>>>(
        (const float4*)key, (const float4*)value,
        (const float4*)key_pages, (const float4*)value_pages,
        (float4*)out_pages);
}